// round 3
// baseline (speedup 1.0000x reference)
#include <cuda_runtime.h>
#include <math.h>

#define BB   4
#define CIN  32
#define COUT 64
#define HH   32
#define WW   32
#define KK   3
#define HP   34
#define WP   34

// Scratch (no allocations allowed): features + duplicated-pair folded weights
__device__ float4 g_feat[BB * CIN * HP * WP];   // (cos x, sin x, cos 3x, sin 3x); pad cells = trig(0)
// Duplicated weights for f32x2 path: per (o, c, kl): 4 x ulonglong2 =
//  { (wx.x,wx.x),(wx.y,wx.y) } { (wx.z,wx.z),(wx.w,wx.w) } { wy.xy dup } { wy.zw dup }
__device__ ulonglong2 g_wd[COUT * CIN * KK * KK * 4];

// ---------------- feature precompute ----------------
// cos^3(x-p) = 3/4[cx*cp + sx*sp] + 1/4[c3x*c3p + s3x*s3p]
__global__ void feat_kernel(const float* __restrict__ x) {
    int i = blockIdx.x * blockDim.x + threadIdx.x;
    const int total = BB * CIN * HP * WP;
    if (i >= total) return;
    int ww = i % WP;
    int hh = (i / WP) % HP;
    int bc = i / (WP * HP);
    float v = 0.0f;  // zero-padding happens BEFORE cos in the reference
    if (hh >= 1 && hh <= HH && ww >= 1 && ww <= WW)
        v = x[(bc * HH + (hh - 1)) * WW + (ww - 1)];
    float s, c;
    sincosf(v, &s, &c);
    float c3 = c * (4.0f * c * c - 3.0f);
    float s3 = s * (3.0f - 4.0f * s * s);
    g_feat[i] = make_float4(c, s, c3, s3);
}

// ---------------- weight folding (emits duplicated-pair layout) ----------------
// probe/out_w layout: (CIN, COUT, K, K) -> idx = ((c*COUT + o)*K + k)*K + l
__device__ __forceinline__ unsigned long long dup_f32(float w) {
    unsigned int b = __float_as_uint(w);
    unsigned long long p;
    asm("mov.b64 %0, {%1, %2};" : "=l"(p) : "r"(b), "r"(b));
    return p;
}
__global__ void weight_kernel(const float* __restrict__ probe,
                              const float* __restrict__ outw) {
    int i = blockIdx.x * blockDim.x + threadIdx.x;
    const int total = CIN * COUT * KK * KK;
    if (i >= total) return;
    int kl = i % (KK * KK);
    int o  = (i / (KK * KK)) % COUT;
    int c  = i / (KK * KK * COUT);

    float sp, cp, sw, cw;
    sincosf(probe[i], &sp, &cp);
    sincosf(outw[i],  &sw, &cw);
    float c3p = cp * (4.0f * cp * cp - 3.0f);
    float s3p = sp * (3.0f - 4.0f * sp * sp);

    float wx0 = 0.75f * cw * cp, wx1 = 0.75f * cw * sp;
    float wx2 = 0.25f * cw * c3p, wx3 = 0.25f * cw * s3p;
    float wy0 = 0.75f * sw * cp, wy1 = 0.75f * sw * sp;
    float wy2 = 0.25f * sw * c3p, wy3 = 0.25f * sw * s3p;

    int base = ((o * CIN + c) * (KK * KK) + kl) * 4;
    g_wd[base + 0] = make_ulonglong2(dup_f32(wx0), dup_f32(wx1));
    g_wd[base + 1] = make_ulonglong2(dup_f32(wx2), dup_f32(wx3));
    g_wd[base + 2] = make_ulonglong2(dup_f32(wy0), dup_f32(wy1));
    g_wd[base + 3] = make_ulonglong2(dup_f32(wy2), dup_f32(wy3));
}

// ---------------- main conv (packed f32x2) ----------------
// Block: 128 threads; covers one b, 2 output channels, 8 rows x 32 cols.
// Each thread: pixel pair (rows r, r+4) packed into f32x2 lanes; 2 o-chan x {x,y}
// -> 4 packed accumulators = 8 fp32 results. Weights duplicated in smem so a
// single LDS.128 yields two (w,w) b64 operands for fma.rn.f32x2.
#define OG 2

__device__ __forceinline__ void ffma2(unsigned long long& acc,
                                      unsigned long long a,
                                      unsigned long long b) {
    asm("fma.rn.f32x2 %0, %1, %2, %0;" : "+l"(acc) : "l"(a), "l"(b));
}
__device__ __forceinline__ unsigned long long pack2(float lo, float hi) {
    unsigned long long p;
    asm("mov.b64 %0, {%1, %2};" : "=l"(p) : "r"(__float_as_uint(lo)), "r"(__float_as_uint(hi)));
    return p;
}

__global__ __launch_bounds__(128) void conv_kernel(float* __restrict__ out) {
    __shared__ ulonglong2 s_wd[OG * CIN * 9 * 4];   // 2304 * 16B = 36.9KB

    const int b    = blockIdx.z;
    const int og   = blockIdx.y;          // 0..31
    const int tile = blockIdx.x;          // 0..3
    const int tid  = threadIdx.x;
    const int obase = og * OG;

    // stage duplicated weights: s index == g index - obase*1152
    {
        const ulonglong2* src = &g_wd[obase * (CIN * 9 * 4)];
        for (int i = tid; i < OG * CIN * 9 * 4; i += 128)
            s_wd[i] = src[i];
    }
    __syncthreads();

    const int col = tid & 31;
    const int r0  = tile * 8 + (tid >> 5);
    const int r1  = r0 + 4;

    unsigned long long accx[OG], accy[OG];
    #pragma unroll
    for (int o = 0; o < OG; o++) { accx[o] = 0ULL; accy[o] = 0ULL; }

    for (int c = 0; c < CIN; c++) {
        const float4* fb = &g_feat[(b * CIN + c) * (HP * WP)];
        #pragma unroll
        for (int k = 0; k < 3; k++) {
            const float4* fr0 = fb + (r0 + k) * WP + col;
            const float4* fr1 = fb + (r1 + k) * WP + col;
            #pragma unroll
            for (int l = 0; l < 3; l++) {
                float4 f0 = fr0[l];
                float4 f1 = fr1[l];
                unsigned long long p0 = pack2(f0.x, f1.x);
                unsigned long long p1 = pack2(f0.y, f1.y);
                unsigned long long p2 = pack2(f0.z, f1.z);
                unsigned long long p3 = pack2(f0.w, f1.w);
                int wbase = (c * 9 + k * 3 + l) * 4;
                #pragma unroll
                for (int o = 0; o < OG; o++) {
                    const ulonglong2* w = &s_wd[o * (CIN * 9 * 4) + wbase];
                    ulonglong2 wx01 = w[0];
                    ulonglong2 wx23 = w[1];
                    ulonglong2 wy01 = w[2];
                    ulonglong2 wy23 = w[3];
                    ffma2(accx[o], p0, wx01.x);
                    ffma2(accx[o], p1, wx01.y);
                    ffma2(accx[o], p2, wx23.x);
                    ffma2(accx[o], p3, wx23.y);
                    ffma2(accy[o], p0, wy01.x);
                    ffma2(accy[o], p1, wy01.y);
                    ffma2(accy[o], p2, wy23.x);
                    ffma2(accy[o], p3, wy23.y);
                }
            }
        }
    }

    #pragma unroll
    for (int o = 0; o < OG; o++) {
        float x0 = __uint_as_float((unsigned int)(accx[o]));
        float x1 = __uint_as_float((unsigned int)(accx[o] >> 32));
        float y0 = __uint_as_float((unsigned int)(accy[o]));
        float y1 = __uint_as_float((unsigned int)(accy[o] >> 32));
        out[((b * COUT + obase + o) * HH + r0) * WW + col] = atan2f(y0, x0);
        out[((b * COUT + obase + o) * HH + r1) * WW + col] = atan2f(y1, x1);
    }
}

extern "C" void kernel_launch(void* const* d_in, const int* in_sizes, int n_in,
                              void* d_out, int out_size) {
    const float* x     = (const float*)d_in[0];   // (4,32,32,32)
    const float* probe = (const float*)d_in[1];   // (1,32,64,1,1,3,3)
    const float* outw  = (const float*)d_in[2];   // (1,32,64,1,1,3,3)
    float* out = (float*)d_out;                   // (4,64,32,32)

    {
        const int total = BB * CIN * HP * WP;
        feat_kernel<<<(total + 255) / 256, 256>>>(x);
    }
    {
        const int total = CIN * COUT * KK * KK;
        weight_kernel<<<(total + 255) / 256, 256>>>(probe, outw);
    }
    {
        dim3 grid(4, COUT / OG, BB);   // (row tiles, o-groups, batch) = 512 CTAs
        conv_kernel<<<grid, 128>>>(out);
    }
    (void)in_sizes; (void)n_in; (void)out_size;
}

// round 4
// speedup vs baseline: 1.4772x; 1.4772x over previous
#include <cuda_runtime.h>
#include <math.h>

#define BB   4
#define CIN  32
#define COUT 64
#define HH   32
#define WW   32
#define KK   3
#define HP   34
#define WP   34

#define FEAT_TOTAL (BB * CIN * HP * WP)        // 147968
#define WGT_TOTAL  (CIN * COUT * KK * KK)      // 18432

// Scratch (no allocations allowed in kernel_launch)
__device__ float4 g_feat[BB * CIN * HP * WP];  // (cos x, sin x, cos 3x, sin 3x); pad cells = trig(0)
__device__ float4 g_wx[COUT * CIN * KK * KK];  // (3/4 cw*cp, 3/4 cw*sp, 1/4 cw*c3p, 1/4 cw*s3p)
__device__ float4 g_wy[COUT * CIN * KK * KK];  // same with sw

// ---------------- fused prep: features + folded weights ----------------
// cos^3(x-p) = 3/4[cx*cp + sx*sp] + 1/4[c3x*c3p + s3x*s3p]
__global__ void prep_kernel(const float* __restrict__ x,
                            const float* __restrict__ probe,
                            const float* __restrict__ outw) {
    int i = blockIdx.x * blockDim.x + threadIdx.x;
    if (i < FEAT_TOTAL) {
        int ww = i % WP;
        int hh = (i / WP) % HP;
        int bc = i / (WP * HP);
        float v = 0.0f;  // zero-padding applied BEFORE cos in the reference
        if (hh >= 1 && hh <= HH && ww >= 1 && ww <= WW)
            v = x[(bc * HH + (hh - 1)) * WW + (ww - 1)];
        float s, c;
        sincosf(v, &s, &c);
        float c3 = c * (4.0f * c * c - 3.0f);
        float s3 = s * (3.0f - 4.0f * s * s);
        g_feat[i] = make_float4(c, s, c3, s3);
    } else {
        int j = i - FEAT_TOTAL;
        if (j >= WGT_TOTAL) return;
        // probe/out_w layout: (CIN, COUT, K, K) -> j = ((c*COUT + o)*K + k)*K + l
        int kl = j % (KK * KK);
        int o  = (j / (KK * KK)) % COUT;
        int c  = j / (KK * KK * COUT);

        float sp, cp, sw, cw;
        sincosf(probe[j], &sp, &cp);
        sincosf(outw[j],  &sw, &cw);
        float c3p = cp * (4.0f * cp * cp - 3.0f);
        float s3p = sp * (3.0f - 4.0f * sp * sp);

        int oidx = (o * CIN + c) * (KK * KK) + kl;   // [o][c][kl] for the conv kernel
        g_wx[oidx] = make_float4(0.75f * cw * cp, 0.75f * cw * sp,
                                 0.25f * cw * c3p, 0.25f * cw * s3p);
        g_wy[oidx] = make_float4(0.75f * sw * cp, 0.75f * sw * sp,
                                 0.25f * sw * c3p, 0.25f * sw * s3p);
    }
}

// ---------------- main conv ----------------
// Block: 128 threads. Each block: one b, OG=2 output channels, 8 rows x 32 cols.
// Each thread: 2 pixels (rows r, r+4) x 2 o-channels x {x,y} -> 8 fp32 accumulators.
// Weights staged in smem (18.4KB -> all 512 CTAs resident, ~3.5 warps/SMSP).
#define OG 2
__global__ __launch_bounds__(128) void conv_kernel(float* __restrict__ out) {
    __shared__ float4 s_w[OG * CIN * 9 * 2];   // 1152 float4 = 18.4KB

    const int b    = blockIdx.z;
    const int og   = blockIdx.y;          // 0..31
    const int tile = blockIdx.x;          // 0..3
    const int tid  = threadIdx.x;
    const int obase = og * OG;

    for (int i = tid; i < OG * CIN * 9 * 2; i += 128) {
        int half = i & 1;
        int idx  = i >> 1;                 // (ol*CIN + c)*9 + kl
        int ol   = idx / (CIN * 9);
        int rest = idx % (CIN * 9);
        int gidx = (obase + ol) * (CIN * 9) + rest;
        s_w[i] = half ? g_wy[gidx] : g_wx[gidx];
    }
    __syncthreads();

    const int col = tid & 31;
    const int r0  = tile * 8 + (tid >> 5);
    const int r1  = r0 + 4;

    float accx0[OG] = {0.f, 0.f};
    float accy0[OG] = {0.f, 0.f};
    float accx1[OG] = {0.f, 0.f};
    float accy1[OG] = {0.f, 0.f};

    for (int c = 0; c < CIN; c++) {
        const float4* fb = &g_feat[(b * CIN + c) * (HP * WP)];
        #pragma unroll
        for (int k = 0; k < 3; k++) {
            const float4* fr0 = fb + (r0 + k) * WP + col;
            const float4* fr1 = fb + (r1 + k) * WP + col;
            #pragma unroll
            for (int l = 0; l < 3; l++) {
                float4 f0 = fr0[l];
                float4 f1 = fr1[l];
                int wbase = (c * 9 + k * 3 + l) * 2;
                #pragma unroll
                for (int o = 0; o < OG; o++) {
                    float4 wx = s_w[o * (CIN * 9 * 2) + wbase];
                    float4 wy = s_w[o * (CIN * 9 * 2) + wbase + 1];
                    accx0[o] = fmaf(f0.x, wx.x, fmaf(f0.y, wx.y, fmaf(f0.z, wx.z, fmaf(f0.w, wx.w, accx0[o]))));
                    accy0[o] = fmaf(f0.x, wy.x, fmaf(f0.y, wy.y, fmaf(f0.z, wy.z, fmaf(f0.w, wy.w, accy0[o]))));
                    accx1[o] = fmaf(f1.x, wx.x, fmaf(f1.y, wx.y, fmaf(f1.z, wx.z, fmaf(f1.w, wx.w, accx1[o]))));
                    accy1[o] = fmaf(f1.x, wy.x, fmaf(f1.y, wy.y, fmaf(f1.z, wy.z, fmaf(f1.w, wy.w, accy1[o]))));
                }
            }
        }
    }

    #pragma unroll
    for (int o = 0; o < OG; o++) {
        out[((b * COUT + obase + o) * HH + r0) * WW + col] = atan2f(accy0[o], accx0[o]);
        out[((b * COUT + obase + o) * HH + r1) * WW + col] = atan2f(accy1[o], accx1[o]);
    }
}

extern "C" void kernel_launch(void* const* d_in, const int* in_sizes, int n_in,
                              void* d_out, int out_size) {
    const float* x     = (const float*)d_in[0];   // (4,32,32,32)
    const float* probe = (const float*)d_in[1];   // (1,32,64,1,1,3,3)
    const float* outw  = (const float*)d_in[2];   // (1,32,64,1,1,3,3)
    float* out = (float*)d_out;                   // (4,64,32,32)

    {
        const int total = FEAT_TOTAL + WGT_TOTAL;
        prep_kernel<<<(total + 255) / 256, 256>>>(x, probe, outw);
    }
    {
        dim3 grid(4, COUT / OG, BB);   // (row tiles, o-groups, batch) = 512 CTAs
        conv_kernel<<<grid, 128>>>(out);
    }
    (void)in_sizes; (void)n_in; (void)out_size;
}

// round 5
// speedup vs baseline: 1.5756x; 1.0667x over previous
#include <cuda_runtime.h>
#include <math.h>

#define BB   4
#define CIN  32
#define COUT 64
#define HH   32
#define WW   32
#define KK   3
#define HP   34
#define WP   34

#define FEAT_TOTAL (BB * CIN * HP * WP)        // 147968
#define WGT_TOTAL  (CIN * COUT * KK * KK)      // 18432

// Scratch (no allocations allowed in kernel_launch)
__device__ float4 g_feat[BB * CIN * HP * WP];  // (cos x, sin x, cos 3x, sin 3x); pad cells = trig(0)
__device__ float4 g_wx[COUT * CIN * KK * KK];  // (3/4 cw*cp, 3/4 cw*sp, 1/4 cw*c3p, 1/4 cw*s3p)
__device__ float4 g_wy[COUT * CIN * KK * KK];  // same with sw

// ---------------- fused prep: features + folded weights ----------------
// cos^3(x-p) = 3/4[cx*cp + sx*sp] + 1/4[c3x*c3p + s3x*s3p]
__global__ void prep_kernel(const float* __restrict__ x,
                            const float* __restrict__ probe,
                            const float* __restrict__ outw) {
    int i = blockIdx.x * blockDim.x + threadIdx.x;
    if (i < FEAT_TOTAL) {
        int ww = i % WP;
        int hh = (i / WP) % HP;
        int bc = i / (WP * HP);
        float v = 0.0f;  // zero-padding applied BEFORE cos in the reference
        if (hh >= 1 && hh <= HH && ww >= 1 && ww <= WW)
            v = x[(bc * HH + (hh - 1)) * WW + (ww - 1)];
        float s, c;
        sincosf(v, &s, &c);
        float c3 = c * (4.0f * c * c - 3.0f);
        float s3 = s * (3.0f - 4.0f * s * s);
        g_feat[i] = make_float4(c, s, c3, s3);
    } else {
        int j = i - FEAT_TOTAL;
        if (j >= WGT_TOTAL) return;
        // probe/out_w layout: (CIN, COUT, K, K) -> j = ((c*COUT + o)*K + k)*K + l
        int kl = j % (KK * KK);
        int o  = (j / (KK * KK)) % COUT;
        int c  = j / (KK * KK * COUT);

        float sp, cp, sw, cw;
        sincosf(probe[j], &sp, &cp);
        sincosf(outw[j],  &sw, &cw);
        float c3p = cp * (4.0f * cp * cp - 3.0f);
        float s3p = sp * (3.0f - 4.0f * sp * sp);

        int oidx = (o * CIN + c) * (KK * KK) + kl;   // [o][c][kl] for the conv kernel
        g_wx[oidx] = make_float4(0.75f * cw * cp, 0.75f * cw * sp,
                                 0.25f * cw * c3p, 0.25f * cw * s3p);
        g_wy[oidx] = make_float4(0.75f * sw * cp, 0.75f * sw * sp,
                                 0.25f * sw * c3p, 0.25f * sw * s3p);
    }
}

// ---------------- main conv (vertical 4-row register reuse) ----------------
// Block: 128 threads = 32 cols x 4 strips; each strip = 4 output rows.
// Each thread: 4 rows x OG=2 o-channels x {x,y} -> 16 fp32 accumulators.
// Per (c,l): 6 feature float4 loads shared across 3 k-offsets x 4 rows.
#define OG 2
__global__ __launch_bounds__(128) void conv_kernel(float* __restrict__ out) {
    __shared__ float4 s_w[OG * CIN * 9 * 2];   // 1152 float4 = 18.4KB

    const int b    = blockIdx.z;
    const int og   = blockIdx.y;          // 0..31
    const int tile = blockIdx.x;          // 0..1  (16-row tiles)
    const int tid  = threadIdx.x;
    const int obase = og * OG;

    for (int i = tid; i < OG * CIN * 9 * 2; i += 128) {
        int half = i & 1;
        int idx  = i >> 1;                 // (ol*CIN + c)*9 + kl
        int ol   = idx / (CIN * 9);
        int rest = idx % (CIN * 9);
        int gidx = (obase + ol) * (CIN * 9) + rest;
        s_w[i] = half ? g_wy[gidx] : g_wx[gidx];
    }
    __syncthreads();

    const int col = tid & 31;
    const int r0  = tile * 16 + (tid >> 5) * 4;   // first of 4 output rows

    float accx[4][OG], accy[4][OG];
    #pragma unroll
    for (int r = 0; r < 4; r++)
        #pragma unroll
        for (int o = 0; o < OG; o++) { accx[r][o] = 0.f; accy[r][o] = 0.f; }

    for (int c = 0; c < CIN; c++) {
        // padded coords: output row r needs padded rows r..r+2; strip needs r0..r0+5
        const float4* fb = &g_feat[(b * CIN + c) * (HP * WP) + r0 * WP + col];
        #pragma unroll
        for (int l = 0; l < 3; l++) {
            float4 f[6];
            #pragma unroll
            for (int j = 0; j < 6; j++)
                f[j] = fb[j * WP + l];
            #pragma unroll
            for (int k = 0; k < 3; k++) {
                const int wbase = (c * 9 + k * 3 + l) * 2;
                #pragma unroll
                for (int o = 0; o < OG; o++) {
                    const float4 wx = s_w[o * (CIN * 9 * 2) + wbase];
                    const float4 wy = s_w[o * (CIN * 9 * 2) + wbase + 1];
                    #pragma unroll
                    for (int r = 0; r < 4; r++) {
                        const float4 fv = f[r + k];
                        accx[r][o] = fmaf(fv.x, wx.x, fmaf(fv.y, wx.y, fmaf(fv.z, wx.z, fmaf(fv.w, wx.w, accx[r][o]))));
                        accy[r][o] = fmaf(fv.x, wy.x, fmaf(fv.y, wy.y, fmaf(fv.z, wy.z, fmaf(fv.w, wy.w, accy[r][o]))));
                    }
                }
            }
        }
    }

    #pragma unroll
    for (int o = 0; o < OG; o++)
        #pragma unroll
        for (int r = 0; r < 4; r++)
            out[((b * COUT + obase + o) * HH + r0 + r) * WW + col] =
                atan2f(accy[r][o], accx[r][o]);
}

extern "C" void kernel_launch(void* const* d_in, const int* in_sizes, int n_in,
                              void* d_out, int out_size) {
    const float* x     = (const float*)d_in[0];   // (4,32,32,32)
    const float* probe = (const float*)d_in[1];   // (1,32,64,1,1,3,3)
    const float* outw  = (const float*)d_in[2];   // (1,32,64,1,1,3,3)
    float* out = (float*)d_out;                   // (4,64,32,32)

    {
        const int total = FEAT_TOTAL + WGT_TOTAL;
        prep_kernel<<<(total + 255) / 256, 256>>>(x, probe, outw);
    }
    {
        dim3 grid(2, COUT / OG, BB);   // (16-row tiles, o-groups, batch) = 256 CTAs
        conv_kernel<<<grid, 128>>>(out);
    }
    (void)in_sizes; (void)n_in; (void)out_size;
}

// round 9
// speedup vs baseline: 2.1063x; 1.3368x over previous
#include <cuda_runtime.h>
#include <cuda_bf16.h>
#include <math.h>
#include <stdint.h>

#define BB   4
#define CIN  32
#define COUT 64
#define HH   32
#define WW   32
#define HP   34
#define WP   34
#define CF   128            // CIN * 4 trig features = K
#define NT   32             // M tiles: 4 b x 8 row-blocks (4 rows x 32 cols = 128 px)
#define NGRP 3              // tap groups (3 taps each)
#define KP   136            // padded smem row stride in bf16 (272B, conflict-free LDSM)
#define TILE_SMEM (128 * KP * 2)   // 34816 B per operand tile

#define FEAT_TOTAL (BB * HP * WP * CIN)   // 147968
#define WGT_TOTAL  (9 * COUT * CIN)       // 18432

// ---------------- device scratch (no allocs allowed) ----------------
__device__ __nv_bfloat16 g_featH[BB * HP * WP * CF];   // padded NHWC, hi part
__device__ __nv_bfloat16 g_featL[BB * HP * WP * CF];   // lo part
__device__ __nv_bfloat16 g_Bh[9][128 * 128];           // weights hi: [tap][n][k] row-major
__device__ __nv_bfloat16 g_Bl[9][128 * 128];           // weights lo
__device__ float g_part[NGRP][NT][128][128];           // [grp][tile][m][n] fp32 partials (6MB)

// ---------------- PTX helpers (sm_80-era; compile for compute_103) ------------
__device__ __forceinline__ uint32_t smem_u32(const void* p) {
    uint32_t a;
    asm("{ .reg .u64 t; cvta.to.shared.u64 t, %1; cvt.u32.u64 %0, t; }" : "=r"(a) : "l"(p));
    return a;
}
#define LDSM_X4(r0, r1, r2, r3, addr) \
    asm volatile("ldmatrix.sync.aligned.m8n8.x4.shared.b16 {%0,%1,%2,%3}, [%4];" \
        : "=r"(r0), "=r"(r1), "=r"(r2), "=r"(r3) : "r"(addr))
#define MMA16816(c, a0, a1, a2, a3, b0, b1) \
    asm volatile("mma.sync.aligned.m16n8k16.row.col.f32.bf16.bf16.f32 " \
        "{%0,%1,%2,%3}, {%4,%5,%6,%7}, {%8,%9}, {%0,%1,%2,%3};" \
        : "+f"((c)[0]), "+f"((c)[1]), "+f"((c)[2]), "+f"((c)[3]) \
        : "r"(a0), "r"(a1), "r"(a2), "r"(a3), "r"(b0), "r"(b1))

// ---------------- prep: trig features (hi/lo bf16) + folded weight matrices ----
// cos^3(x-p) = 3/4[cx*cp + sx*sp] + 1/4[c3x*c3p + s3x*s3p]
__global__ void prep_kernel(const float* __restrict__ x,
                            const float* __restrict__ probe,
                            const float* __restrict__ outw) {
    int i = blockIdx.x * blockDim.x + threadIdx.x;
    if (i < FEAT_TOTAL) {
        int c = i & 31;
        int t = i >> 5;
        int pc = t % WP; t /= WP;
        int pr = t % HP;
        int b  = t / HP;
        float v = 0.0f;  // zero-pad applied BEFORE cos in the reference
        if (pr >= 1 && pr <= HH && pc >= 1 && pc <= WW)
            v = x[((b * CIN + c) * HH + (pr - 1)) * WW + (pc - 1)];
        float s, cv;
        sincosf(v, &s, &cv);
        float f[4];
        f[0] = cv; f[1] = s;
        f[2] = cv * (4.0f * cv * cv - 3.0f);
        f[3] = s * (3.0f - 4.0f * s * s);
        int base = ((b * HP + pr) * WP + pc) * CF + c * 4;
        #pragma unroll
        for (int q = 0; q < 4; q++) {
            float a = f[q];
            __nv_bfloat16 h = __float2bfloat16(a);
            g_featH[base + q] = h;
            g_featL[base + q] = __float2bfloat16(a - __bfloat162float(h));
        }
    } else {
        int j = i - FEAT_TOTAL;
        if (j >= WGT_TOTAL) return;
        int c  = j % CIN;
        int o  = (j / CIN) % COUT;
        int kl = j / (CIN * COUT);
        int widx = (c * COUT + o) * 9 + kl;   // (1,CIN,COUT,1,1,3,3) flat

        float sp, cp, sw, cw;
        sincosf(probe[widx], &sp, &cp);
        sincosf(outw[widx],  &sw, &cw);
        float c3p = cp * (4.0f * cp * cp - 3.0f);
        float s3p = sp * (3.0f - 4.0f * sp * sp);
        float wx[4] = {0.75f * cw * cp, 0.75f * cw * sp, 0.25f * cw * c3p, 0.25f * cw * s3p};
        float wy[4] = {0.75f * sw * cp, 0.75f * sw * sp, 0.25f * sw * c3p, 0.25f * sw * s3p};

        #pragma unroll
        for (int f = 0; f < 4; f++) {
            int col = c * 4 + f;
            {
                float a = wx[f];
                __nv_bfloat16 h = __float2bfloat16(a);
                g_Bh[kl][o * 128 + col] = h;
                g_Bl[kl][o * 128 + col] = __float2bfloat16(a - __bfloat162float(h));
            }
            {
                float a = wy[f];
                __nv_bfloat16 h = __float2bfloat16(a);
                g_Bh[kl][(o + 64) * 128 + col] = h;
                g_Bl[kl][(o + 64) * 128 + col] = __float2bfloat16(a - __bfloat162float(h));
            }
        }
    }
}

// ---------------- gemm: per-CTA (M-tile, tap-group) -> fp32 partial D ----------
// 256 threads = 8 warps; warp w owns m-rows [w*16, w*16+16) x all 128 n.
// smem: Ah | Al | Bh | Bl, each 128 rows x KP bf16 (row stride 272B).
__global__ __launch_bounds__(256) void gemm_kernel() {
    extern __shared__ unsigned char smem[];
    unsigned char* sAh = smem;
    unsigned char* sAl = smem + TILE_SMEM;
    unsigned char* sBh = smem + 2 * TILE_SMEM;
    unsigned char* sBl = smem + 3 * TILE_SMEM;
    const uint32_t uAh = smem_u32(sAh);
    const uint32_t uAl = uAh + TILE_SMEM;
    const uint32_t uBh = uAh + 2 * TILE_SMEM;
    const uint32_t uBl = uAh + 3 * TILE_SMEM;

    const int tid  = threadIdx.x;
    const int wid  = tid >> 5;
    const int ln   = tid & 31;
    const int tile = blockIdx.x;          // 0..31
    const int grp  = blockIdx.y;          // 0..2
    const int b    = tile >> 3;
    const int r0   = (tile & 7) * 4;      // first output row of this tile
    const int m0   = wid * 16;

    // ldmatrix lane addressing (K-major operands, non-trans):
    // A x4 mats: (m0-7,k0-7)(m8-15,k0-7)(m0-7,k8-15)(m8-15,k8-15)
    const uint32_t aoff = (uint32_t)(((m0 + (ln & 15)) * KP + (ln >> 4) * 8) * 2);
    // B x4 mats: (n0-7,k0-7)(n0-7,k8-15)(n8-15,k0-7)(n8-15,k8-15)
    const int brow = (ln & 7) + ((ln >> 4) & 1) * 8;
    const int bcol = ((ln >> 3) & 1) * 8;

    float c[16][4];
    #pragma unroll
    for (int f = 0; f < 16; f++)
        #pragma unroll
        for (int q = 0; q < 4; q++) c[f][q] = 0.0f;

    for (int it = 0; it < 3; it++) {
        const int kl = grp * 3 + it;
        const int k = kl / 3, l = kl % 3;

        if (it > 0) __syncthreads();   // mma of prior tap done before restage

        // stage: 2048 16B-chunks per tile; i -> (row m, chunk j)
        for (int i = tid; i < 2048; i += 256) {
            int m = i >> 4, j = i & 15;
            uint32_t doff = (uint32_t)(m * (KP * 2) + j * 16);
            // A: pixel (b, r0+(m>>5)+k, (m&31)+l), contiguous 256B feature vector
            size_t abyte = ((size_t)((b * HP + (r0 + (m >> 5) + k)) * WP + ((m & 31) + l)) * CF + j * 8) * 2;
            *(uint4*)(sAh + doff) = *(const uint4*)((const unsigned char*)g_featH + abyte);
            *(uint4*)(sAl + doff) = *(const uint4*)((const unsigned char*)g_featL + abyte);
            // B: row n = m, 16 bf16 chunk j
            size_t bbyte = ((size_t)m * 128 + j * 8) * 2;
            *(uint4*)(sBh + doff) = *(const uint4*)((const unsigned char*)g_Bh[kl] + bbyte);
            *(uint4*)(sBl + doff) = *(const uint4*)((const unsigned char*)g_Bl[kl] + bbyte);
        }
        __syncthreads();

        #pragma unroll
        for (int ks = 0; ks < 8; ks++) {
            const uint32_t ka = (uint32_t)(ks * 32);   // 16 bf16 = 32B
            uint32_t ah0, ah1, ah2, ah3, al0, al1, al2, al3;
            LDSM_X4(ah0, ah1, ah2, ah3, uAh + aoff + ka);
            LDSM_X4(al0, al1, al2, al3, uAl + aoff + ka);
            #pragma unroll
            for (int nf = 0; nf < 8; nf++) {
                const uint32_t boff = (uint32_t)(((nf * 16 + brow) * KP + bcol) * 2) + ka;
                uint32_t bh0, bh1, bh2, bh3, bl0, bl1, bl2, bl3;
                LDSM_X4(bh0, bh1, bh2, bh3, uBh + boff);
                LDSM_X4(bl0, bl1, bl2, bl3, uBl + boff);
                MMA16816(c[2 * nf],     ah0, ah1, ah2, ah3, bh0, bh1);
                MMA16816(c[2 * nf + 1], ah0, ah1, ah2, ah3, bh2, bh3);
                MMA16816(c[2 * nf],     al0, al1, al2, al3, bh0, bh1);
                MMA16816(c[2 * nf + 1], al0, al1, al2, al3, bh2, bh3);
                MMA16816(c[2 * nf],     ah0, ah1, ah2, ah3, bl0, bl1);
                MMA16816(c[2 * nf + 1], ah0, ah1, ah2, ah3, bl2, bl3);
            }
        }
    }

    // epilogue: D frag -> g_part[grp][tile][m][n]
    float* dst = &g_part[grp][tile][0][0];
    const int row = ln >> 2;
    const int colb = (ln & 3) * 2;
    #pragma unroll
    for (int nf = 0; nf < 16; nf++) {
        const int n0 = nf * 8 + colb;
        *(float2*)&dst[(m0 + row) * 128 + n0]     = make_float2(c[nf][0], c[nf][1]);
        *(float2*)&dst[(m0 + row + 8) * 128 + n0] = make_float2(c[nf][2], c[nf][3]);
    }
}

// ---------------- combine: sum 3 partials + atan2 (smem transpose) ------------
__global__ __launch_bounds__(256) void combine_kernel(float* __restrict__ out) {
    __shared__ float s_x[128][65];
    __shared__ float s_y[128][65];
    const int t = blockIdx.x;     // tile
    const int tid = threadIdx.x;

    const float* p0 = &g_part[0][t][0][0];
    const float* p1 = &g_part[1][t][0][0];
    const float* p2 = &g_part[2][t][0][0];
    for (int i = tid; i < 128 * 128; i += 256) {
        float v = p0[i] + p1[i] + p2[i];
        int m = i >> 7, n = i & 127;
        if (n < 64) s_x[m][n] = v;
        else        s_y[m][n - 64] = v;
    }
    __syncthreads();

    const int b = t >> 3;
    const int hbase = (t & 7) * 4;
    for (int i = tid; i < 64 * 128; i += 256) {
        int o = i >> 7, m = i & 127;
        float ang = atan2f(s_y[m][o], s_x[m][o]);
        int h = hbase + (m >> 5), w = m & 31;
        out[((b * COUT + o) * HH + h) * WW + w] = ang;
    }
}

// ---------------- launch ----------------
extern "C" void kernel_launch(void* const* d_in, const int* in_sizes, int n_in,
                              void* d_out, int out_size) {
    const float* x     = (const float*)d_in[0];
    const float* probe = (const float*)d_in[1];
    const float* outw  = (const float*)d_in[2];
    float* out = (float*)d_out;

    const int SMEM = 4 * TILE_SMEM;   // 139264 B
    cudaFuncSetAttribute(gemm_kernel, cudaFuncAttributeMaxDynamicSharedMemorySize, SMEM);

    {
        const int total = FEAT_TOTAL + WGT_TOTAL;
        prep_kernel<<<(total + 255) / 256, 256>>>(x, probe, outw);
    }
    {
        dim3 grid(NT, NGRP);
        gemm_kernel<<<grid, 256, SMEM>>>();
    }
    combine_kernel<<<NT, 256>>>(out);
    (void)in_sizes; (void)n_in; (void)out_size;
}